// round 11
// baseline (speedup 1.0000x reference)
#include <cuda_runtime.h>
#include <cstdint>

#define HW       64
#define CH       3
#define NPIX     (HW * HW)              // 4096
#define NELEM    (NPIX * CH)            // 12288 floats per image
#define ROWS_C   32                     // output rows per CTA (half image)
#define BROWS    (ROWS_C + 2)           // staged rows incl. reflect halo = 34
#define T_A      256
#define SROWS    8                      // rows per thread strip (4 strips)
#define STG_W    (BROWS * 48)           // float4 gmem words to stage = 1632
#define SMEM_A   (32 * 4 + BROWS * HW * 16)   // red scratch + padded tile
#define LOG2E    1.4426950408889634f

__device__ __forceinline__ float ex2f(float x) {
    float r; asm("ex2.approx.ftz.f32 %0, %1;" : "=f"(r) : "f"(x)); return r;
}
__device__ __forceinline__ float rcpf(float x) {
    float r; asm("rcp.approx.ftz.f32 %0, %1;" : "=f"(r) : "f"(x)); return r;
}
__device__ __forceinline__ unsigned int smem_u32(const void* p) {
    unsigned int a;
    asm("{ .reg .u64 t; cvta.to.shared.u64 t, %1; cvt.u32.u64 %0, t; }"
        : "=r"(a) : "l"(p));
    return a;
}
__device__ __forceinline__ void st_peer_f32(unsigned int laddr, unsigned int peer_rank, float v) {
    unsigned int r;
    asm("mapa.shared::cluster.u32 %0, %1, %2;" : "=r"(r) : "r"(laddr), "r"(peer_rank));
    asm volatile("st.shared::cluster.f32 [%0], %1;" :: "r"(r), "f"(v) : "memory");
}

__global__ void __launch_bounds__(T_A, 4) __cluster_dims__(2, 1, 1)
dns_kernel(const float* __restrict__ images,
           const float* __restrict__ params,
           const float* __restrict__ kptr,
           float* __restrict__ out)
{
    extern __shared__ float smem[];
    // red layout: [0..7] noise warp partials, [8..15] det warp partials,
    //             [16..17] own totals, [18..19] peer totals
    float*  red  = smem;
    float*  buf  = smem + 32;
    float4* buf4 = (float4*)buf;

    const int tid = threadIdx.x;
    unsigned int rank;
    asm("mov.u32 %0, %%cluster_ctarank;" : "=r"(rank));

    const int img  = blockIdx.x >> 1;
    const int row0 = (int)rank * ROWS_C;          // first output row of CTA
    const float* base = images + (size_t)img * NELEM;
    float*       dst  = out    + (size_t)img * NELEM;

    // ---- stage BROWS rows (reflect halo) into padded float4 smem ----
    #pragma unroll
    for (int it = 0; it < (STG_W + T_A - 1) / T_A; ++it) {
        const int f = tid + it * T_A;             // 0..1631
        if (f < STG_W) {
            const int row  = f / 48;
            const int col4 = f - row * 48;
            int srow = row0 + row - 1;
            srow = abs(srow);                      // -1 -> 1
            srow = 63 - abs(63 - srow);            // 64 -> 62
            const float4 v = ((const float4*)(base + srow * (HW * CH)))[col4];
            const float  w[4] = { v.x, v.y, v.z, v.w };
            const int wbase = col4 * 4;
            #pragma unroll
            for (int k = 0; k < 4; ++k) {
                const int widx = wbase + k;
                const int pix  = widx / 3;
                const int ch   = widx - pix * 3;
                buf[(row * HW + pix) * 4 + ch] = w[k];
            }
        }
    }

    // ---- per-image parameters (uniform; L2-resident) ----
    const float* p = params + img * 7;
    const float sigma_s = fminf(fmaxf(p[0], 0.2f), 5.0f);
    const float sigma_r = fminf(fmaxf(p[1], 0.01f), 1.0f);
    const float sigma_f = fminf(fmaxf(p[2], 0.2f), 3.0f);
    const float lam     = fminf(fmaxf(p[3], 0.1f), 2.0f);
    const float tau     = fminf(fmaxf(p[4], 0.5f), 5.0f);
    const float gain    = fminf(fmaxf(p[5], 0.2f), 2.0f);
    const float offset  = fminf(fmaxf(p[6], 0.01f), 1.0f);
    const float k_pos   = fmaxf(fabsf(*kptr), 1.0f);

    const float ls2      = (-0.5f / (sigma_s * sigma_s)) * LOG2E;
    const float b_edge   = ls2;
    const float b_corner = 2.0f * ls2;
    const float cR       = (-0.5f / (sigma_r * sigma_r)) * LOG2E;

    const float ef   = __expf(-0.5f / (sigma_f * sigma_f));
    const float ef2  = ef * ef;
    const float ifn  = rcpf(1.0f + 2.0f * ef);
    const float ifn2 = ifn * ifn;

    const float invtau2L2 = rcpf(tau * tau) * LOG2E;
    const float kL2       = k_pos * LOG2E;

    __syncthreads();

    float sum_noise = 0.0f, sum_det = 0.0f;

    // ---- vertical strip with 3x3 sliding register window ----
    {
        const int x     = tid & 63;               // column (fixed per thread)
        const int strip = tid >> 6;               // 0..3
        const int br0   = strip * SROWS + 1;      // buffer row of first pixel
        const int xm = abs(x - 1);
        const int xp = 63 - abs(62 - x);

        // preload rows br0-1 and br0 (3 columns each)
        float4 a0m = buf4[(br0 - 1) * HW + xm];
        float4 a0c = buf4[(br0 - 1) * HW + x ];
        float4 a0p = buf4[(br0 - 1) * HW + xp];
        float4 a1m = buf4[ br0      * HW + xm];
        float4 a1c = buf4[ br0      * HW + x ];
        float4 a1p = buf4[ br0      * HW + xp];

        #pragma unroll
        for (int j = 0; j < SROWS; ++j) {
            const int brow = br0 + j;
            float4 a2m = buf4[(brow + 1) * HW + xm];
            float4 a2c = buf4[(brow + 1) * HW + x ];
            float4 a2p = buf4[(brow + 1) * HW + xp];

            const float4 C = a1c;

            float bn0 = C.x, bn1 = C.y, bn2 = C.z, bden = 1.0f;
            float e40 = 0.f, e41 = 0.f, e42 = 0.f;
            float c40 = 0.f, c41 = 0.f, c42 = 0.f;

            #define TAP(T, BIAS, A0, A1, A2)                                   \
            {                                                                  \
                const float d0 = T.x - C.x, d1 = T.y - C.y, d2 = T.z - C.z;    \
                const float cds = d0 * d0 + d1 * d1 + d2 * d2;                 \
                const float kk = ex2f(fmaf(cds, cR, BIAS));                    \
                bden += kk;                                                    \
                bn0 = fmaf(kk, T.x, bn0);                                      \
                bn1 = fmaf(kk, T.y, bn1);                                      \
                bn2 = fmaf(kk, T.z, bn2);                                      \
                A0 += T.x; A1 += T.y; A2 += T.z;                               \
            }
            TAP(a0c, b_edge,   e40, e41, e42)   // up
            TAP(a2c, b_edge,   e40, e41, e42)   // down
            TAP(a1m, b_edge,   e40, e41, e42)   // left
            TAP(a1p, b_edge,   e40, e41, e42)   // right
            TAP(a0m, b_corner, c40, c41, c42)
            TAP(a0p, b_corner, c40, c41, c42)
            TAP(a2m, b_corner, c40, c41, c42)
            TAP(a2p, b_corner, c40, c41, c42)
            #undef TAP

            const float inv_den = rcpf(bden);
            const float cen[3]  = { C.x, C.y, C.z };
            const float bnum[3] = { bn0, bn1, bn2 };
            const float gr[3]   = { fmaf(ef, e40, fmaf(ef2, c40, C.x)),
                                    fmaf(ef, e41, fmaf(ef2, c41, C.y)),
                                    fmaf(ef, e42, fmaf(ef2, c42, C.z)) };
            const int obase = ((row0 + strip * SROWS + j) * HW + x) * 3;
            #pragma unroll
            for (int c = 0; c < CH; ++c) {
                const float bf     = bnum[c] * inv_den;
                const float detail = fmaf(-ifn2, gr[c], cen[c]);
                const float ad     = fabsf(detail);
                const float denom  = fmaxf(cen[c] + offset, 1e-5f);
                const float ne     = fminf(ad * gain * rcpf(denom), 10.0f);
                sum_noise += ne;
                sum_det   += ad;
                const float em    = ex2f(-(ne * ne) * invtau2L2);
                const float t1    = 1.0f - em;
                const float nmask = t1 * t1;
                const float dmask = rcpf(1.0f + ex2f(-kL2 * (ad - 0.002f)));
                const float v     = fmaf(lam * detail, nmask * dmask, bf);
                dst[obase + c] = fminf(fmaxf(v, 1e-5f), 1.0f);
            }

            // slide the window down one row
            a0m = a1m; a0c = a1c; a0p = a1p;
            a1m = a2m; a1c = a2c; a1p = a2p;
        }
    }

    // ---- CTA reduction of partial sums ----
    #pragma unroll
    for (int o = 16; o > 0; o >>= 1) {
        sum_noise += __shfl_xor_sync(0xFFFFFFFFu, sum_noise, o);
        sum_det   += __shfl_xor_sync(0xFFFFFFFFu, sum_det, o);
    }
    if ((tid & 31) == 0) {
        red[tid >> 5]       = sum_noise;          // 8 warps
        red[8 + (tid >> 5)] = sum_det;
    }
    __syncthreads();

    if (tid == 0) {
        float tn = 0.f, td = 0.f;
        #pragma unroll
        for (int w = 0; w < T_A / 32; ++w) { tn += red[w]; td += red[8 + w]; }
        red[16] = tn;  red[17] = td;              // own totals
        // deposit into peer CTA's red[18..19]
        const unsigned int l18 = smem_u32(&red[18]);
        st_peer_f32(l18,     rank ^ 1u, tn);
        st_peer_f32(l18 + 4, rank ^ 1u, td);
    }

    // cluster barrier: release own deposits, acquire peer's
    asm volatile("barrier.cluster.arrive.aligned;" ::: "memory");
    asm volatile("barrier.cluster.wait.aligned;"   ::: "memory");
    __syncthreads();   // red[16..19] visible to all threads in this CTA

    const float tot_n = red[16] + red[18];
    const float tot_d = red[17] + red[19];
    const float inv_n = 1.0f / (float)NELEM;
    const bool skip = (tot_n * inv_n < 1e-4f) || (tot_d * inv_n < 1e-4f);

    // ---- rare path: rewrite own half with clip(x) ----
    if (skip) {
        const float4* s4 = (const float4*)(base + row0 * (HW * CH));
        float*        d  = dst + row0 * (HW * CH);
        #pragma unroll
        for (int i = 0; i < (ROWS_C * HW * CH / 4) / T_A; ++i) {
            const float4 v = s4[tid + i * T_A];
            const float w[4] = { v.x, v.y, v.z, v.w };
            const int wb = (tid + i * T_A) * 4;
            #pragma unroll
            for (int k = 0; k < 4; ++k)
                d[wb + k] = fminf(fmaxf(w[k], 1e-5f), 1.0f);
        }
    }
}

extern "C" void kernel_launch(void* const* d_in, const int* in_sizes, int n_in,
                              void* d_out, int out_size)
{
    const float* images = (const float*)d_in[0];
    const float* params = (const float*)d_in[1];
    const float* kptr   = (const float*)d_in[2];
    float*       out    = (float*)d_out;

    const int nimg = in_sizes[1] / 7;  // B*P = 512

    cudaFuncSetAttribute(dns_kernel,
                         cudaFuncAttributeMaxDynamicSharedMemorySize, SMEM_A);
    dns_kernel<<<nimg * 2, T_A, SMEM_A>>>(images, params, kptr, out);
}

// round 12
// speedup vs baseline: 1.4870x; 1.4870x over previous
#include <cuda_runtime.h>
#include <cstdint>

#define HW       64
#define CH       3
#define NPIX     (HW * HW)              // 4096
#define NELEM    (NPIX * CH)            // 12288 floats per image
#define ROWS_C   32                     // output rows per CTA (half image)
#define BROWS    (ROWS_C + 2)           // staged rows incl. reflect halo = 34
#define BPIX     (BROWS * HW)           // 2176 staged pixels
#define T_A      256
#define PPT      ((ROWS_C * HW) / T_A)  // 8 pixels per thread
#define STG_W    (BROWS * 48)           // float4 gmem words to stage = 1632
#define SMEM_A   (32 * 4 + BROWS * HW * 16)   // red scratch + padded tile
#define LOG2E    1.4426950408889634f

__device__ __forceinline__ float ex2f(float x) {
    float r; asm("ex2.approx.ftz.f32 %0, %1;" : "=f"(r) : "f"(x)); return r;
}
__device__ __forceinline__ float rcpf(float x) {
    float r; asm("rcp.approx.ftz.f32 %0, %1;" : "=f"(r) : "f"(x)); return r;
}
__device__ __forceinline__ float tanhf_approx(float x) {
    float r; asm("tanh.approx.f32 %0, %1;" : "=f"(r) : "f"(x)); return r;
}
__device__ __forceinline__ unsigned int smem_u32(const void* p) {
    unsigned int a;
    asm("{ .reg .u64 t; cvta.to.shared.u64 t, %1; cvt.u32.u64 %0, t; }"
        : "=r"(a) : "l"(p));
    return a;
}
__device__ __forceinline__ void st_peer_f32(unsigned int laddr, unsigned int peer_rank, float v) {
    unsigned int r;
    asm("mapa.shared::cluster.u32 %0, %1, %2;" : "=r"(r) : "r"(laddr), "r"(peer_rank));
    asm volatile("st.shared::cluster.f32 [%0], %1;" :: "r"(r), "f"(v) : "memory");
}

__global__ void __launch_bounds__(T_A, 6) __cluster_dims__(2, 1, 1)
dns_kernel(const float* __restrict__ images,
           const float* __restrict__ params,
           const float* __restrict__ kptr,
           float* __restrict__ out)
{
    extern __shared__ float smem[];
    // red layout: [0..7] noise warp partials, [8..15] det warp partials,
    //             [16..17] own totals, [18..19] peer totals
    float*  red  = smem;
    float*  buf  = smem + 32;
    float4* buf4 = (float4*)buf;

    const int tid = threadIdx.x;
    unsigned int rank;
    asm("mov.u32 %0, %%cluster_ctarank;" : "=r"(rank));

    const int img  = blockIdx.x >> 1;
    const int row0 = (int)rank * ROWS_C;          // first output row of CTA
    const float* base = images + (size_t)img * NELEM;
    float*       dst  = out    + (size_t)img * NELEM;

    // ---- stage BROWS rows (reflect halo) into padded float4 smem ----
    #pragma unroll
    for (int it = 0; it < (STG_W + T_A - 1) / T_A; ++it) {
        const int f = tid + it * T_A;             // 0..1631
        if (f < STG_W) {
            const int row  = f / 48;
            const int col4 = f - row * 48;
            int srow = row0 + row - 1;
            srow = abs(srow);                      // -1 -> 1
            srow = 63 - abs(63 - srow);            // 64 -> 62
            const float4 v = ((const float4*)(base + srow * (HW * CH)))[col4];
            const float  w[4] = { v.x, v.y, v.z, v.w };
            const int wbase = col4 * 4;
            #pragma unroll
            for (int k = 0; k < 4; ++k) {
                const int widx = wbase + k;
                const int pix  = widx / 3;
                const int ch   = widx - pix * 3;
                buf[(row * HW + pix) * 4 + ch] = w[k];
            }
        }
    }
    __syncthreads();

    // ---- norm pass: .w = |rgb|^2, full-vector load AND store (no scalar
    //      aliasing of the float4 tile) ----
    #pragma unroll
    for (int it = 0; it < (BPIX + T_A - 1) / T_A; ++it) {
        const int f = tid + it * T_A;             // 0..2175
        if (f < BPIX) {
            float4 v = buf4[f];
            v.w = fmaf(v.x, v.x, fmaf(v.y, v.y, v.z * v.z));
            buf4[f] = v;
        }
    }

    // ---- per-image parameters (uniform; L2-resident) ----
    const float* p = params + img * 7;
    const float sigma_s = fminf(fmaxf(p[0], 0.2f), 5.0f);
    const float sigma_r = fminf(fmaxf(p[1], 0.01f), 1.0f);
    const float sigma_f = fminf(fmaxf(p[2], 0.2f), 3.0f);
    const float lam     = fminf(fmaxf(p[3], 0.1f), 2.0f);
    const float tau     = fminf(fmaxf(p[4], 0.5f), 5.0f);
    const float gain    = fminf(fmaxf(p[5], 0.2f), 2.0f);
    const float offset  = fminf(fmaxf(p[6], 0.01f), 1.0f);
    const float k_pos   = fmaxf(fabsf(*kptr), 1.0f);

    const float ls2      = (-0.5f / (sigma_s * sigma_s)) * LOG2E;
    const float b_edge   = ls2;
    const float b_corner = 2.0f * ls2;
    const float cR       = (-0.5f / (sigma_r * sigma_r)) * LOG2E;
    const float m2       = -2.0f * cR;

    const float ef   = __expf(-0.5f / (sigma_f * sigma_f));
    const float ef2  = ef * ef;
    const float ifn  = rcpf(1.0f + 2.0f * ef);
    const float ifn2 = ifn * ifn;

    const float invtau2L2 = rcpf(tau * tau) * LOG2E;
    const float khalf     = 0.5f * k_pos;

    __syncthreads();

    float sum_noise = 0.0f, sum_det = 0.0f;

    #pragma unroll
    for (int i = 0; i < PPT; ++i) {
        const int lp = tid + i * T_A;             // 0..2047 in half-image
        const int ly = lp >> 6, x = lp & 63;
        const int br = ly + 1;
        const int xm = abs(x - 1);
        const int xp = 63 - abs(62 - x);
        const int r0 = br * HW, rm = r0 - HW, rp = r0 + HW;

        const float4 C = buf4[r0 + x];
        // arg(t) = cR*(|t|^2 + |C|^2 - 2 t.C) + bias  as a 4-FMA chain
        const float a0 = m2 * C.x, a1 = m2 * C.y, a2 = m2 * C.z;
        const float cbE = fmaf(cR, C.w, b_edge);
        const float cbC = fmaf(cR, C.w, b_corner);

        float bn0 = C.x, bn1 = C.y, bn2 = C.z, bden = 1.0f;
        float e40 = 0.f, e41 = 0.f, e42 = 0.f;
        float c40 = 0.f, c41 = 0.f, c42 = 0.f;

        #define TAP(IDX, CB, A0, A1, A2)                                   \
        {                                                                  \
            const float4 t = buf4[IDX];                                    \
            float arg = fmaf(cR, t.w, CB);                                 \
            arg = fmaf(a2, t.z, arg);                                      \
            arg = fmaf(a1, t.y, arg);                                      \
            arg = fmaf(a0, t.x, arg);                                      \
            const float kk = ex2f(arg);                                    \
            bden += kk;                                                    \
            bn0 = fmaf(kk, t.x, bn0);                                      \
            bn1 = fmaf(kk, t.y, bn1);                                      \
            bn2 = fmaf(kk, t.z, bn2);                                      \
            A0 += t.x; A1 += t.y; A2 += t.z;                               \
        }
        TAP(rm + x,  cbE, e40, e41, e42)   // up
        TAP(rp + x,  cbE, e40, e41, e42)   // down
        TAP(r0 + xm, cbE, e40, e41, e42)   // left
        TAP(r0 + xp, cbE, e40, e41, e42)   // right
        TAP(rm + xm, cbC, c40, c41, c42)
        TAP(rm + xp, cbC, c40, c41, c42)
        TAP(rp + xm, cbC, c40, c41, c42)
        TAP(rp + xp, cbC, c40, c41, c42)
        #undef TAP

        const float inv_den = rcpf(bden);
        const float cen[3]  = { C.x, C.y, C.z };
        const float bnum[3] = { bn0, bn1, bn2 };
        const float gr[3]   = { fmaf(ef, e40, fmaf(ef2, c40, C.x)),
                                fmaf(ef, e41, fmaf(ef2, c41, C.y)),
                                fmaf(ef, e42, fmaf(ef2, c42, C.z)) };
        const int obase = ((row0 + ly) * HW + x) * 3;
        #pragma unroll
        for (int c = 0; c < CH; ++c) {
            const float bf     = bnum[c] * inv_den;
            const float detail = fmaf(-ifn2, gr[c], cen[c]);
            const float ad     = fabsf(detail);
            const float denom  = fmaxf(cen[c] + offset, 1e-5f);
            const float ne     = fminf(ad * gain * rcpf(denom), 10.0f);
            sum_noise += ne;
            sum_det   += ad;
            const float em    = ex2f(-(ne * ne) * invtau2L2);
            const float t1    = 1.0f - em;
            const float nmask = t1 * t1;
            // sigmoid(k*(ad-0.002)) = 0.5*tanh(0.5*k*(ad-0.002)) + 0.5
            const float dmask = fmaf(0.5f, tanhf_approx(khalf * (ad - 0.002f)), 0.5f);
            const float v     = fmaf(lam * detail, nmask * dmask, bf);
            dst[obase + c] = fminf(fmaxf(v, 1e-5f), 1.0f);
        }
    }

    // ---- CTA reduction of partial sums ----
    #pragma unroll
    for (int o = 16; o > 0; o >>= 1) {
        sum_noise += __shfl_xor_sync(0xFFFFFFFFu, sum_noise, o);
        sum_det   += __shfl_xor_sync(0xFFFFFFFFu, sum_det, o);
    }
    if ((tid & 31) == 0) {
        red[tid >> 5]       = sum_noise;          // 8 warps
        red[8 + (tid >> 5)] = sum_det;
    }
    __syncthreads();

    if (tid == 0) {
        float tn = 0.f, td = 0.f;
        #pragma unroll
        for (int w = 0; w < T_A / 32; ++w) { tn += red[w]; td += red[8 + w]; }
        red[16] = tn;  red[17] = td;              // own totals
        // deposit into peer CTA's red[18..19]
        const unsigned int l18 = smem_u32(&red[18]);
        st_peer_f32(l18,     rank ^ 1u, tn);
        st_peer_f32(l18 + 4, rank ^ 1u, td);
    }

    // cluster barrier: release own deposits, acquire peer's
    asm volatile("barrier.cluster.arrive.aligned;" ::: "memory");
    asm volatile("barrier.cluster.wait.aligned;"   ::: "memory");
    __syncthreads();   // red[16..19] visible to all threads in this CTA

    const float tot_n = red[16] + red[18];
    const float tot_d = red[17] + red[19];
    const float inv_n = 1.0f / (float)NELEM;
    const bool skip = (tot_n * inv_n < 1e-4f) || (tot_d * inv_n < 1e-4f);

    // ---- rare path: rewrite own half with clip(x) ----
    if (skip) {
        const float4* s4 = (const float4*)(base + row0 * (HW * CH));
        float*        d  = dst + row0 * (HW * CH);
        #pragma unroll
        for (int i = 0; i < (ROWS_C * HW * CH / 4) / T_A; ++i) {
            const float4 v = s4[tid + i * T_A];
            const float w[4] = { v.x, v.y, v.z, v.w };
            const int wb = (tid + i * T_A) * 4;
            #pragma unroll
            for (int k = 0; k < 4; ++k)
                d[wb + k] = fminf(fmaxf(w[k], 1e-5f), 1.0f);
        }
    }
}

extern "C" void kernel_launch(void* const* d_in, const int* in_sizes, int n_in,
                              void* d_out, int out_size)
{
    const float* images = (const float*)d_in[0];
    const float* params = (const float*)d_in[1];
    const float* kptr   = (const float*)d_in[2];
    float*       out    = (float*)d_out;

    const int nimg = in_sizes[1] / 7;  // B*P = 512

    cudaFuncSetAttribute(dns_kernel,
                         cudaFuncAttributeMaxDynamicSharedMemorySize, SMEM_A);
    dns_kernel<<<nimg * 2, T_A, SMEM_A>>>(images, params, kptr, out);
}